// round 17
// baseline (speedup 1.0000x reference)
#include <cuda_runtime.h>
#include <cuda_bf16.h>
#include <math.h>
#include <stdint.h>

// Problem constants
#define NROWS 32768      // rows in x (and in x_pair)
#define DDIM  256        // feature dim
#define NB    128        // 2B batches
#define MSZ   512        // mask size
#define EPSN  1e-8f

// Scratch
__device__ __align__(16) __nv_bfloat16 g_z[(size_t)NB * MSZ * DDIM];
__device__ float g_pos_partials[4096];
__device__ float g_row[NB][4][128];        // row-sums of exp per (b, i-block)
__device__ float g_col[NB][4][3][128];     // col-sum contribs: [b][dst block][src ti]
__device__ float g_neg_partials[NB];
__device__ int   g_cnt[NB];
__device__ int   g_done;

__device__ __forceinline__ uint32_t smem_u32(const void* p) {
    uint32_t a;
    asm("{ .reg .u64 t; cvta.to.shared.u64 t, %1; cvt.u32.u64 %0, t; }" : "=r"(a) : "l"(p));
    return a;
}

// ---------------------------------------------------------------------------
// Kernel 1: per-row L2 normalize -> bf16 per-batch layout + pos partials
// Block = (b, gi-group of 8): writes are 4KB-contiguous per block.
// ---------------------------------------------------------------------------
__device__ __forceinline__ void store_bf16x4(__nv_bfloat16* dst, int idx4,
                                             float4 v, float scale) {
    __nv_bfloat162 lo = __floats2bfloat162_rn(v.x * scale, v.y * scale);
    __nv_bfloat162 hi = __floats2bfloat162_rn(v.z * scale, v.w * scale);
    uint2 packed;
    packed.x = *reinterpret_cast<uint32_t*>(&lo);
    packed.y = *reinterpret_cast<uint32_t*>(&hi);
    reinterpret_cast<uint2*>(dst)[idx4] = packed;
}

__global__ __launch_bounds__(256) void k_prep(const float* __restrict__ x,
                                              const float* __restrict__ xp) {
    int wid  = threadIdx.x >> 5;
    int lane = threadIdx.x & 31;
    int b    = blockIdx.x >> 5;        // 0..127
    int g    = blockIdx.x & 31;        // 0..31
    int gi   = g * 8 + wid;            // 0..255
    int row  = gi * 128 + b;

    if (threadIdx.x == 0 && blockIdx.x < NB) g_cnt[blockIdx.x] = 0;
    if (threadIdx.x == 0 && blockIdx.x == NB) g_done = 0;

    const float4* xr = reinterpret_cast<const float4*>(x)  + (size_t)row * (DDIM / 4);
    const float4* pr = reinterpret_cast<const float4*>(xp) + (size_t)row * (DDIM / 4);

    float4 a0 = xr[lane];
    float4 a1 = xr[lane + 32];
    float4 b0 = pr[lane];
    float4 b1 = pr[lane + 32];

    float sx = a0.x*a0.x + a0.y*a0.y + a0.z*a0.z + a0.w*a0.w
             + a1.x*a1.x + a1.y*a1.y + a1.z*a1.z + a1.w*a1.w;
    float sp = b0.x*b0.x + b0.y*b0.y + b0.z*b0.z + b0.w*b0.w
             + b1.x*b1.x + b1.y*b1.y + b1.z*b1.z + b1.w*b1.w;
    float dp = a0.x*b0.x + a0.y*b0.y + a0.z*b0.z + a0.w*b0.w
             + a1.x*b1.x + a1.y*b1.y + a1.z*b1.z + a1.w*b1.w;

    #pragma unroll
    for (int o = 16; o > 0; o >>= 1) {
        sx += __shfl_xor_sync(0xFFFFFFFFu, sx, o);
        sp += __shfl_xor_sync(0xFFFFFFFFu, sp, o);
        dp += __shfl_xor_sync(0xFFFFFFFFu, dp, o);
    }

    float ix = 1.0f / fmaxf(sqrtf(sx), EPSN);
    float ip = 1.0f / fmaxf(sqrtf(sp), EPSN);

    // z[b, gi] = x[gi*128 + b]; z[b, 256+gi] = x_pair[gi*128 + b]
    __nv_bfloat16* on = g_z + ((size_t)b * MSZ + gi) * DDIM;
    __nv_bfloat16* op = g_z + ((size_t)b * MSZ + 256 + gi) * DDIM;
    store_bf16x4(on, lane,      a0, ix);
    store_bf16x4(on, lane + 32, a1, ix);
    store_bf16x4(op, lane,      b0, ip);
    store_bf16x4(op, lane + 32, b1, ip);

    __shared__ float sm[8];
    if (lane == 0) sm[wid] = dp * ix * ip;
    __syncthreads();
    if (threadIdx.x == 0) {
        float t = 0.f;
        #pragma unroll
        for (int i = 0; i < 8; ++i) t += sm[i];
        g_pos_partials[blockIdx.x] = t;
    }
}

// ---------------------------------------------------------------------------
// Kernel 2: symmetric gram, upper-triangle tiles, pipelined epilogue
// CTA = (ti, b): grid 512 (heavy ti=0 first), 256 threads
// Epilogue of tile t interleaved into MMA loop of tile t+1 (pacc registers).
// Final scalar loss computed by last-arriving CTA (no k_final kernel).
// ---------------------------------------------------------------------------
#define AB_STRIDE 528                 // 512B row + 16B pad (conflict-free ldmatrix)
#define TILE_B    (128 * AB_STRIDE)   // 67,584 B
#define SMEM_DYN  (3 * TILE_B)        // 202,752 B

__device__ __forceinline__ void cp_tile(char* dst, const char* src, int tid) {
    uint32_t d = smem_u32(dst);
    #pragma unroll
    for (int i = 0; i < 16; ++i) {
        int idx = tid + i * 256;       // 0..4095: 128 rows x 32 segs of 16B
        int row = idx >> 5;
        int seg = idx & 31;
        asm volatile("cp.async.cg.shared.global [%0], [%1], 16;"
                     :: "r"(d + row * AB_STRIDE + seg * 16),
                        "l"(src + (size_t)row * 512 + seg * 16) : "memory");
    }
}
#define CP_COMMIT() asm volatile("cp.async.commit_group;" ::: "memory")

__device__ __forceinline__ void ldsm_x4(uint32_t* r, uint32_t addr) {
    asm volatile("ldmatrix.sync.aligned.m8n8.x4.shared.b16 {%0,%1,%2,%3}, [%4];"
                 : "=r"(r[0]), "=r"(r[1]), "=r"(r[2]), "=r"(r[3]) : "r"(addr));
}
__device__ __forceinline__ void mma16816(float* c, const uint32_t* a,
                                         uint32_t b0, uint32_t b1) {
    asm volatile("mma.sync.aligned.m16n8k16.row.col.f32.bf16.bf16.f32 "
                 "{%0,%1,%2,%3}, {%4,%5,%6,%7}, {%8,%9}, {%0,%1,%2,%3};"
                 : "+f"(c[0]), "+f"(c[1]), "+f"(c[2]), "+f"(c[3])
                 : "r"(a[0]), "r"(a[1]), "r"(a[2]), "r"(a[3]), "r"(b0), "r"(b1));
}

// exp + mask + row/col accumulate for one (mi, ni) quad of the prev tile
__device__ __forceinline__ void epi_pair(const float (&a4)[4], int mi, int ni,
        bool pdiag, int warp_m, int warp_n, int lane,
        float (&racc)[4], float (&colp)[8][2])
{
    float e00 = __expf(a4[0] * 2.f);
    float e01 = __expf(a4[1] * 2.f);
    float e10 = __expf(a4[2] * 2.f);
    float e11 = __expf(a4[3] * 2.f);
    if (pdiag) {
        const int li0 = warp_m * 32 + mi * 16 + (lane >> 2);
        const int lj  = warp_n * 64 + ni * 8 + (lane & 3) * 2;
        if (li0 == lj)         e00 = 0.f;
        if (li0 == lj + 1)     e01 = 0.f;
        if (li0 + 8 == lj)     e10 = 0.f;
        if (li0 + 8 == lj + 1) e11 = 0.f;
    }
    racc[mi * 2 + 0] += e00 + e01;
    racc[mi * 2 + 1] += e10 + e11;
    colp[ni][0] += e00 + e10;
    colp[ni][1] += e01 + e11;
}

template<bool EPI>
__device__ __forceinline__ void tile_mma(uint32_t aBase, uint32_t bBase,
        float (&acc)[2][8][4], const float (&pacc)[2][8][4], bool pdiag,
        int warp_m, int warp_n, int lane, float (&racc)[4], float (&colp)[8][2])
{
    #pragma unroll
    for (int mi = 0; mi < 2; ++mi)
        #pragma unroll
        for (int ni = 0; ni < 8; ++ni)
            #pragma unroll
            for (int q = 0; q < 4; ++q) acc[mi][ni][q] = 0.f;

    #pragma unroll
    for (int ks = 0; ks < 16; ++ks) {
        uint32_t af[2][4];
        ldsm_x4(af[0], aBase + ks * 32);
        ldsm_x4(af[1], aBase + 16 * AB_STRIDE + ks * 32);
        #pragma unroll
        for (int p = 0; p < 4; ++p) {
            uint32_t bf[4];
            ldsm_x4(bf, bBase + p * 16 * AB_STRIDE + ks * 32);
            #pragma unroll
            for (int mi = 0; mi < 2; ++mi) {
                mma16816(acc[mi][p * 2 + 0], af[mi], bf[0], bf[1]);
                mma16816(acc[mi][p * 2 + 1], af[mi], bf[2], bf[3]);
            }
        }
        if (EPI)   // overlap prev tile's epilogue with this tile's MMA
            epi_pair(pacc[ks >> 3][ks & 7], ks >> 3, ks & 7, pdiag,
                     warp_m, warp_n, lane, racc, colp);
    }
}

__device__ __forceinline__ void colp_store(float (&colp)[8][2], int b, int dst,
        int ti, int warp_m, int warp_n, int lane, int tid, float (*s_col)[128])
{
    #pragma unroll
    for (int ni = 0; ni < 8; ++ni)
        #pragma unroll
        for (int q = 0; q < 2; ++q) {
            colp[ni][q] += __shfl_xor_sync(0xFFFFFFFFu, colp[ni][q], 4);
            colp[ni][q] += __shfl_xor_sync(0xFFFFFFFFu, colp[ni][q], 8);
            colp[ni][q] += __shfl_xor_sync(0xFFFFFFFFu, colp[ni][q], 16);
        }
    if (lane < 4) {
        #pragma unroll
        for (int ni = 0; ni < 8; ++ni) {
            int col = warp_n * 64 + ni * 8 + lane * 2;
            s_col[warp_m][col]     = colp[ni][0];
            s_col[warp_m][col + 1] = colp[ni][1];
        }
    }
    __syncthreads();
    if (tid < 128) {
        float cs = ((s_col[0][tid] + s_col[1][tid])
                  + (s_col[2][tid] + s_col[3][tid]));
        g_col[b][dst][ti][tid] = cs;      // written exactly once
    }
    __syncthreads();
    #pragma unroll
    for (int ni = 0; ni < 8; ++ni) { colp[ni][0] = 0.f; colp[ni][1] = 0.f; }
}

__global__ __launch_bounds__(256, 1) void k_neg(float* __restrict__ out) {
    extern __shared__ char smraw[];
    char* sA = smraw;
    char* sBb[2] = { smraw + TILE_B, smraw + 2 * TILE_B };
    __shared__ float s_part[2][128];
    __shared__ float s_col[4][128];
    __shared__ float s_red[8];
    __shared__ float rp[256], rn[256];
    __shared__ int   s_last, s_gdone;

    const int tid    = threadIdx.x;
    const int w      = tid >> 5;
    const int lane   = tid & 31;
    const int ti     = blockIdx.x >> 7;         // heavy (ti=0) CTAs first
    const int b      = blockIdx.x & 127;
    const int warp_m = w & 3;
    const int warp_n = w >> 2;

    const char* zb = reinterpret_cast<const char*>(g_z) + (size_t)b * MSZ * DDIM * 2;

    cp_tile(sA, zb + (size_t)ti * 128 * 512, tid);
    CP_COMMIT();
    if (ti < 3) {
        cp_tile(sBb[(ti + 1) & 1], zb + (size_t)(ti + 1) * 128 * 512, tid);
        CP_COMMIT();
        asm volatile("cp.async.wait_group 1;" ::: "memory");   // A ready
    } else {
        asm volatile("cp.async.wait_group 0;" ::: "memory");
    }
    __syncthreads();

    const uint32_t aBase = smem_u32(sA)
        + (uint32_t)(warp_m * 32 + (lane & 15)) * AB_STRIDE + (uint32_t)(lane >> 4) * 16;
    const uint32_t bOff  =
          (uint32_t)(warp_n * 64 + (lane >> 4) * 8 + (lane & 7)) * AB_STRIDE
        + (uint32_t)((lane >> 3) & 1) * 16;

    float racc[4] = {0.f, 0.f, 0.f, 0.f};
    float colp[8][2];
    #pragma unroll
    for (int ni = 0; ni < 8; ++ni) { colp[ni][0] = 0.f; colp[ni][1] = 0.f; }
    float acc[2][8][4], pacc[2][8][4];
    bool have_prev = false, prev_diag = false;
    int  ptj = 0;

    for (int tj = ti; tj <= 3; ++tj) {
        const bool diag = (tj == ti);
        if (!diag) {
            __syncthreads();   // prior MMA reads of target buffer complete
            if (tj < 3) {
                cp_tile(sBb[(tj + 1) & 1], zb + (size_t)(tj + 1) * 128 * 512, tid);
                CP_COMMIT();
                asm volatile("cp.async.wait_group 1;" ::: "memory");
            } else {
                asm volatile("cp.async.wait_group 0;" ::: "memory");
            }
            __syncthreads();   // B(tj) visible
        }
        const uint32_t bBase = (diag ? smem_u32(sA) : smem_u32(sBb[tj & 1])) + bOff;

        if (have_prev)
            tile_mma<true >(aBase, bBase, acc, pacc, prev_diag,
                            warp_m, warp_n, lane, racc, colp);
        else
            tile_mma<false>(aBase, bBase, acc, pacc, prev_diag,
                            warp_m, warp_n, lane, racc, colp);

        if (have_prev) {
            if (!prev_diag) {
                colp_store(colp, b, ptj, ti, warp_m, warp_n, lane, tid, s_col);
            } else {   // discard diag tile's column pollution
                #pragma unroll
                for (int ni = 0; ni < 8; ++ni) { colp[ni][0] = 0.f; colp[ni][1] = 0.f; }
            }
        }
        #pragma unroll
        for (int mi = 0; mi < 2; ++mi)
            #pragma unroll
            for (int ni = 0; ni < 8; ++ni)
                #pragma unroll
                for (int q = 0; q < 4; ++q) pacc[mi][ni][q] = acc[mi][ni][q];
        prev_diag = diag; ptj = tj; have_prev = true;
    }

    // exposed tail: epilogue of the last tile
    #pragma unroll
    for (int e = 0; e < 16; ++e)
        epi_pair(pacc[e >> 3][e & 7], e >> 3, e & 7, prev_diag,
                 warp_m, warp_n, lane, racc, colp);
    if (!prev_diag)
        colp_store(colp, b, ptj, ti, warp_m, warp_n, lane, tid, s_col);

    // row partials: quad reduce, fixed-slot combine, store once
    #pragma unroll
    for (int s = 0; s < 4; ++s) {
        racc[s] += __shfl_xor_sync(0xFFFFFFFFu, racc[s], 1);
        racc[s] += __shfl_xor_sync(0xFFFFFFFFu, racc[s], 2);
    }
    if ((lane & 3) == 0) {
        #pragma unroll
        for (int s = 0; s < 4; ++s) {
            int row = warp_m * 32 + (s >> 1) * 16 + (s & 1) * 8 + (lane >> 2);
            s_part[warp_n][row] = racc[s];
        }
    }
    __syncthreads();
    if (tid < 128) g_row[b][ti][tid] = s_part[0][tid] + s_part[1][tid];

    // per-batch completion: 4th CTA computes the batch's logsum (deterministic)
    __threadfence();
    __syncthreads();
    if (tid == 0) s_last = atomicAdd(&g_cnt[b], 1);
    __syncthreads();
    if (s_last == 3) {
        __threadfence();
        float lg = 0.f;
        #pragma unroll
        for (int rr2 = 0; rr2 < 2; ++rr2) {
            int r  = tid + rr2 * 256;
            int t  = r >> 7;
            int rr = r & 127;
            float v = g_row[b][t][rr];
            for (int src = 0; src < t; ++src) v += g_col[b][t][src][rr];
            lg += logf(v);
        }
        #pragma unroll
        for (int o = 16; o > 0; o >>= 1) lg += __shfl_xor_sync(0xFFFFFFFFu, lg, o);
        if (lane == 0) s_red[w] = lg;
        __syncthreads();
        if (tid == 0) {
            float t = 0.f;
            #pragma unroll
            for (int i = 0; i < 8; ++i) t += s_red[i];
            g_neg_partials[b] = t;
        }
    }

    // global completion: 512th CTA computes the final scalar (deterministic)
    __threadfence();
    __syncthreads();
    if (tid == 0) s_gdone = atomicAdd(&g_done, 1);
    __syncthreads();
    if (s_gdone == 511) {
        __threadfence();
        float sp = 0.f;
        #pragma unroll
        for (int i = 0; i < 16; ++i) sp += g_pos_partials[tid + i * 256];
        rp[tid] = sp;
        rn[tid] = (tid < NB) ? g_neg_partials[tid] : 0.f;
        __syncthreads();
        for (int o = 128; o > 0; o >>= 1) {
            if (tid < o) { rp[tid] += rp[tid + o]; rn[tid] += rn[tid + o]; }
            __syncthreads();
        }
        if (tid == 0) {
            float loss_neg = rn[0] / (float)(NB * MSZ);
            float loss_pos = rp[0] * 2.0f / (float)NROWS;
            out[0] = loss_neg - loss_pos;
        }
    }
}

// ---------------------------------------------------------------------------
extern "C" void kernel_launch(void* const* d_in, const int* in_sizes, int n_in,
                              void* d_out, int out_size) {
    const float* x  = (const float*)d_in[0];
    const float* xp = (const float*)d_in[1];
    float* out = (float*)d_out;

    cudaFuncSetAttribute(k_neg, cudaFuncAttributeMaxDynamicSharedMemorySize, SMEM_DYN);

    k_prep<<<NROWS / 8, 256>>>(x, xp);
    k_neg<<<NB * 4, 256, SMEM_DYN>>>(out);
}